// round 10
// baseline (speedup 1.0000x reference)
#include <cuda_runtime.h>
#include <cstddef>

// JPEG 8x8 blockify + orthonormal 2D DCT-II + QF quantization.
// image: [16,1,1024,1024] f32, qf: [16] f32 -> out [16,64,128,128] f32.
//
// R10 = R8 (2 threads/block, __ldcg/__stcs) with a cheaper row transform:
// exchange ROWS once after the column DCT (16 shfl, the information-minimum)
// so each thread owns 4 full rows and runs 4 plain dct8 butterflies with
// immediate coefficients. Replaces R8's 32 shfl + per-k coefficient scheme.
// Scale table padded by 4 words so h=0/h=1 LDS.128 hit disjoint banks.

#define A0 0.35355339059327373f  // 1/sqrt(8)
#define H1 0.49039264020161522f  // cos(1*pi/16)/2
#define H2 0.46193976625564337f  // cos(2*pi/16)/2
#define H3 0.41573480615127262f  // cos(3*pi/16)/2
#define H4 0.35355339059327376f  // cos(4*pi/16)/2
#define H5 0.27778511650980111f  // cos(5*pi/16)/2
#define H6 0.19134171618254489f  // cos(6*pi/16)/2
#define H7 0.09754516100806413f  // cos(7*pi/16)/2

__constant__ float c_qtab[64] = {
    16.f, 11.f, 10.f, 16.f, 24.f, 40.f, 51.f, 61.f,
    12.f, 12.f, 14.f, 19.f, 26.f, 58.f, 60.f, 55.f,
    14.f, 13.f, 16.f, 24.f, 40.f, 57.f, 69.f, 56.f,
    14.f, 17.f, 22.f, 29.f, 51.f, 87.f, 80.f, 62.f,
    18.f, 22.f, 37.f, 56.f, 68.f, 109.f, 103.f, 77.f,
    24.f, 36.f, 55.f, 64.f, 81.f, 104.f, 113.f, 92.f,
    49.f, 64.f, 78.f, 87.f, 103.f, 121.f, 120.f, 101.f,
    72.f, 92.f, 95.f, 98.f, 112.f, 100.f, 103.f, 99.f};

__device__ __forceinline__ void dct8(float& x0, float& x1, float& x2, float& x3,
                                     float& x4, float& x5, float& x6, float& x7) {
    float e0 = x0 + x7, e1 = x1 + x6, e2 = x2 + x5, e3 = x3 + x4;
    float o0 = x0 - x7, o1 = x1 - x6, o2 = x2 - x5, o3 = x3 - x4;
    float ee0 = e0 + e3, ee1 = e1 + e2;
    float eo0 = e0 - e3, eo1 = e1 - e2;
    x0 = A0 * (ee0 + ee1);
    x4 = H4 * (ee0 - ee1);
    x2 = H2 * eo0 + H6 * eo1;
    x6 = H6 * eo0 - H2 * eo1;
    x1 = H1 * o0 + H3 * o1 + H5 * o2 + H7 * o3;
    x3 = H3 * o0 - H7 * o1 - H1 * o2 - H5 * o3;
    x5 = H5 * o0 - H1 * o1 + H7 * o2 + H3 * o3;
    x7 = H7 * o0 - H5 * o1 + H3 * o2 - H1 * o3;
}

__global__ __launch_bounds__(256, 4) void jpeg_dct_kernel(
    const float* __restrict__ img,
    const float* __restrict__ qf,
    float* __restrict__ out) {
    // 68 floats: planes 0..31 at [0..32), planes 32..63 at [36..68).
    // +4-word pad => h=0 and h=1 LDS.128 reads land on disjoint banks.
    __shared__ __align__(16) float sScale[68];

    int tid = blockIdx.x * 256 + threadIdx.x;
    int b = tid >> 15;  // 2 threads/block, 32768 threads per image; CTA-uniform

    if (threadIdx.x < 64) {
        float q = qf[b];
        float factor = (q < 50.0f) ? (5000.0f / q) : (200.0f - 2.0f * q);
        int idx = threadIdx.x + ((threadIdx.x >> 5) << 2);  // +4 pad for upper half
        sScale[idx] = 100.0f / (c_qtab[threadIdx.x] * factor);
    }
    __syncthreads();

    int bid = tid >> 1;      // 8x8 block index
    int h = tid & 1;         // half: owns columns 4h..4h+3, then rows 4h..4h+3
    int hb = (bid >> 7) & 127;
    int wb = bid & 127;
    bool hi = (h != 0);

    // Loads: lane pair covers 32B; warp covers 512B contiguous per row.
    const float* p = img + ((size_t)b << 20) + (size_t)hb * 8192 + wb * 8 + h * 4;

    float x[8][4];
#pragma unroll
    for (int r = 0; r < 8; r++) {
        float4 v = __ldcg((const float4*)(p + (size_t)r * 1024));
        x[r][0] = v.x - 128.0f;
        x[r][1] = v.y - 128.0f;
        x[r][2] = v.z - 128.0f;
        x[r][3] = v.w - 128.0f;
    }

    // Column transform: thread-local, own 4 columns.
#pragma unroll
    for (int c = 0; c < 4; c++) {
        dct8(x[0][c], x[1][c], x[2][c], x[3][c],
             x[4][c], x[5][c], x[6][c], x[7][c]);
    }

    // Row transform: thread h finishes rows k = 4h+i (i=0..3).
    // Exchange the information-minimum 16 values: per i, send the row the
    // partner needs (4 shfl), keep own 4, and assemble the full 8-column row
    // with selects. Rows i and i+4 of x both die at iteration i.
    int sbase = hi ? 36 : 0;                  // padded scale offset
    float* ob = out + ((size_t)b << 20) + (size_t)(h * 32) * 16384 + hb * 128 + wb;

#pragma unroll
    for (int i = 0; i < 4; i++) {
        float s0 = hi ? x[i][0] : x[i + 4][0];
        float s1 = hi ? x[i][1] : x[i + 4][1];
        float s2 = hi ? x[i][2] : x[i + 4][2];
        float s3 = hi ? x[i][3] : x[i + 4][3];
        float r0 = __shfl_xor_sync(0xffffffffu, s0, 1);
        float r1 = __shfl_xor_sync(0xffffffffu, s1, 1);
        float r2 = __shfl_xor_sync(0xffffffffu, s2, 1);
        float r3 = __shfl_xor_sync(0xffffffffu, s3, 1);

        // Row k = i+4h, columns 0..7:
        //   h=0: cols 0..3 = own x[i][*],   cols 4..7 = partner (r*)
        //   h=1: cols 0..3 = partner (r*),  cols 4..7 = own x[i+4][*]
        float v0 = hi ? r0 : x[i][0];
        float v1 = hi ? r1 : x[i][1];
        float v2 = hi ? r2 : x[i][2];
        float v3 = hi ? r3 : x[i][3];
        float v4 = hi ? x[i + 4][0] : r0;
        float v5 = hi ? x[i + 4][1] : r1;
        float v6 = hi ? x[i + 4][2] : r2;
        float v7 = hi ? x[i + 4][3] : r3;

        dct8(v0, v1, v2, v3, v4, v5, v6, v7);

        float4 sa = *(const float4*)&sScale[sbase + i * 8];
        float4 sb = *(const float4*)&sScale[sbase + i * 8 + 4];
        float* ok = ob + (size_t)(i * 8) * 16384;
        __stcs(ok,                     v0 * sa.x);
        __stcs(ok + (size_t)1 * 16384, v1 * sa.y);
        __stcs(ok + (size_t)2 * 16384, v2 * sa.z);
        __stcs(ok + (size_t)3 * 16384, v3 * sa.w);
        __stcs(ok + (size_t)4 * 16384, v4 * sb.x);
        __stcs(ok + (size_t)5 * 16384, v5 * sb.y);
        __stcs(ok + (size_t)6 * 16384, v6 * sb.z);
        __stcs(ok + (size_t)7 * 16384, v7 * sb.w);
    }
}

extern "C" void kernel_launch(void* const* d_in, const int* in_sizes, int n_in,
                              void* d_out, int out_size) {
    const float* img = (const float*)d_in[0];
    const float* qf = (const float*)d_in[1];
    float* out = (float*)d_out;
    // 16 images * 16384 blocks * 2 threads = 524288 threads -> 2048 CTAs
    jpeg_dct_kernel<<<2048, 256>>>(img, qf, out);
}